// round 5
// baseline (speedup 1.0000x reference)
#include <cuda_runtime.h>
#include <math.h>

#define H 2048
#define S 2048
#define V 50257

// ---------------- device scratch (allocation-free rule) ----------------
__device__ __align__(16) float g_part[64 * H];   // enc column-sum partials
__device__ __align__(16) float g_cat[2 * H];     // [embedded ; attn_applied]
__device__ __align__(16) float g_x[H];           // relu(comb output)
__device__ __align__(16) float g_gh[3 * H];      // w_hh @ h0 dots
__device__ __align__(16) float g_gx[3 * H];      // w_ih @ x dots
__device__ __align__(16) float g_h[H];           // h_new
__device__ __align__(16) float g_logits[V];
__device__ float g_shift;

__device__ __forceinline__ float warp_sum(float v) {
    #pragma unroll
    for (int o = 16; o > 0; o >>= 1) v += __shfl_xor_sync(0xffffffffu, v, o);
    return v;
}

// dot of one K=2048 row vs smem vector; explicit 8-deep batches (MLP=8).
__device__ __forceinline__ float dot2048(const float4* __restrict__ wr,
                                         const float4* __restrict__ xs,
                                         int lane) {
    float acc = 0.f;
    #pragma unroll
    for (int ph = 0; ph < 2; ++ph) {
        float4 wb[8];
        #pragma unroll
        for (int i = 0; i < 8; ++i) wb[i] = wr[lane + 32 * (ph * 8 + i)];
        #pragma unroll
        for (int i = 0; i < 8; ++i) {
            float4 x = xs[lane + 32 * (ph * 8 + i)];
            acc += wb[i].x * x.x + wb[i].y * x.y + wb[i].z * x.z + wb[i].w * x.w;
        }
    }
    return acc;
}

// K1: fused independent work. grid 258 x 1024 threads.
//   b in [0,192)   : gh = w_hh @ h0  (6144 rows; row = warp*192 + b, exact)
//   b in [192,256) : enc column-sum partials (64 chunks of 32 rows)
//   b in [256,258) : embedding gather -> g_cat[0..H)
__global__ __launch_bounds__(1024) void k1_fused(
        const float* __restrict__ w_hh, const float* __restrict__ hprev,
        const float* __restrict__ enc,  const float* __restrict__ emb,
        const int* __restrict__ input_id) {
    __shared__ __align__(16) float xs[H];
    int b = blockIdx.x, tid = threadIdx.x;
    if (b < 192) {
        xs[tid] = hprev[tid]; xs[tid + 1024] = hprev[tid + 1024];
        __syncthreads();
        int w = tid >> 5, lane = tid & 31;
        int row = w * 192 + b;                         // 0..6143, balanced
        float d = dot2048((const float4*)(w_hh + (size_t)row * H),
                          (const float4*)xs, lane);
        d = warp_sum(d);
        if (lane == 0) g_gh[row] = d;
    } else if (b < 256) {
        int chunk = b - 192;                           // 0..63
        int r0 = chunk * 32;
        int c0 = tid, c1 = tid + 1024;
        float s0 = 0.f, s1 = 0.f;
        #pragma unroll
        for (int i = 0; i < 32; ++i) {
            const float* row = enc + (size_t)(r0 + i) * H;
            s0 += row[c0]; s1 += row[c1];
        }
        g_part[chunk * H + c0] = s0;
        g_part[chunk * H + c1] = s1;
    } else {
        int j = (b - 256) * 1024 + tid;                // 0..2047
        g_cat[j] = emb[(size_t)input_id[0] * H + j];
    }
}

// K2: finish column sums -> g_cat[H..2H). 2 blocks x 1024.
__global__ void k2_finish_cat() {
    int col = blockIdx.x * 1024 + threadIdx.x;
    float s = 0.f;
    #pragma unroll
    for (int c = 0; c < 64; ++c) s += g_part[c * H + col];
    g_cat[H + col] = s;
}

// K3: x = relu(comb_w @ cat + comb_b), K=4096. 2 warps per row (K-split),
// 128 blocks x 1024 thr: block handles 16 rows.
__global__ __launch_bounds__(1024) void k3_comb(const float* __restrict__ w,
                                                const float* __restrict__ b) {
    __shared__ __align__(16) float xs[2 * H];          // 16 KB
    __shared__ float part[32];
    int tid = threadIdx.x;
    ((float4*)xs)[tid] = ((const float4*)g_cat)[tid];  // 1024 * 16B = 16KB
    __syncthreads();
    int wpid = tid >> 5, lane = tid & 31;
    int rlocal = wpid >> 1, half = wpid & 1;
    int row = blockIdx.x * 16 + rlocal;                // 0..2047
    float d = dot2048((const float4*)(w + (size_t)row * 2 * H + (size_t)half * H),
                      (const float4*)(xs + half * H), lane);
    d = warp_sum(d);
    if (lane == 0) part[wpid] = d;
    __syncthreads();
    if (tid < 16) {
        int r = blockIdx.x * 16 + tid;
        g_x[r] = fmaxf(part[2 * tid] + part[2 * tid + 1] + b[r], 0.f);
    }
}

// K4: gx = w_ih @ x. 192 blocks x 1024; row = warp*192 + b (6144 exact).
__global__ __launch_bounds__(1024) void k4_wih(const float* __restrict__ w_ih) {
    __shared__ __align__(16) float xs[H];
    int tid = threadIdx.x;
    xs[tid] = g_x[tid]; xs[tid + 1024] = g_x[tid + 1024];
    __syncthreads();
    int w = tid >> 5, lane = tid & 31;
    int row = w * 192 + blockIdx.x;
    float d = dot2048((const float4*)(w_ih + (size_t)row * H),
                      (const float4*)xs, lane);
    d = warp_sum(d);
    if (lane == 0) g_gx[row] = d;
}

// K5: elementwise GRU gates -> g_h. 2 blocks x 1024.
__global__ void k5_gates(const float* __restrict__ b_ih, const float* __restrict__ b_hh,
                         const float* __restrict__ hprev) {
    int j = blockIdx.x * 1024 + threadIdx.x;
    float pre_r = g_gx[j]     + b_ih[j]     + g_gh[j]     + b_hh[j];
    float pre_z = g_gx[H + j] + b_ih[H + j] + g_gh[H + j] + b_hh[H + j];
    float r = 1.f / (1.f + expf(-pre_r));
    float z = 1.f / (1.f + expf(-pre_z));
    float n = tanhf(g_gx[2 * H + j] + b_ih[2 * H + j]
                    + r * (g_gh[2 * H + j] + b_hh[2 * H + j]));
    g_h[j] = (1.f - z) * n + z * hprev[j];
}

// K6: logits = out_w @ h_new + out_b. 296 blocks x 1024, grid-stride rows.
__global__ __launch_bounds__(1024) void k6_out(const float* __restrict__ w,
                                               const float* __restrict__ b) {
    __shared__ __align__(16) float xs[H];
    int tid = threadIdx.x;
    xs[tid] = g_h[tid]; xs[tid + 1024] = g_h[tid + 1024];
    __syncthreads();
    int wpid = tid >> 5, lane = tid & 31;
    for (int row = wpid * 296 + blockIdx.x; row < V; row += 296 * 32) {
        float d = dot2048((const float4*)(w + (size_t)row * H),
                          (const float4*)xs, lane);
        d = warp_sum(d);
        if (lane == 0) g_logits[row] = d + b[row];
    }
}

// K7: single-block online logsumexp over g_logits -> g_shift.
__global__ void k7_lse() {
    __shared__ float sm[1024], ss[1024];
    int tid = threadIdx.x;
    float m = -INFINITY, s = 0.f;
    for (int i = tid; i < V; i += 1024) {
        float l = g_logits[i];
        float nm = fmaxf(m, l);
        s = s * expf(m - nm) + expf(l - nm);
        m = nm;
    }
    sm[tid] = m; ss[tid] = s;
    __syncthreads();
    for (int o = 512; o > 0; o >>= 1) {
        if (tid < o) {
            float m2 = sm[tid + o], s2 = ss[tid + o];
            float nm = fmaxf(sm[tid], m2);
            ss[tid] = ss[tid] * expf(sm[tid] - nm) + s2 * expf(m2 - nm);
            sm[tid] = nm;
        }
        __syncthreads();
    }
    if (tid == 0) g_shift = sm[0] + logf(ss[0]);
}

// K8: write outputs: log_probs (V) | h_new (H) | attn_weights=1 (S)
__global__ void k8_write(float* __restrict__ out, int out_size) {
    int i = blockIdx.x * 256 + threadIdx.x;
    if (i >= out_size) return;
    if (i < V)            out[i] = g_logits[i] - g_shift;
    else if (i < V + H)   out[i] = g_h[i - V];
    else                  out[i] = 1.0f;
}

extern "C" void kernel_launch(void* const* d_in, const int* in_sizes, int n_in,
                              void* d_out, int out_size) {
    const int*   input_id = (const int*)  d_in[0];
    const float* hidden   = (const float*)d_in[1];   // (1,1,H)
    const float* enc      = (const float*)d_in[2];   // (S,H)
    const float* emb      = (const float*)d_in[3];   // (V,H)
    // d_in[4], d_in[5]: attn_w / attn_b — provably dead (softmax over singleton)
    const float* comb_w   = (const float*)d_in[6];
    const float* comb_b   = (const float*)d_in[7];
    const float* w_ih     = (const float*)d_in[8];
    const float* w_hh     = (const float*)d_in[9];
    const float* b_ih     = (const float*)d_in[10];
    const float* b_hh     = (const float*)d_in[11];
    const float* out_w    = (const float*)d_in[12];
    const float* out_b    = (const float*)d_in[13];
    float* out = (float*)d_out;

    k1_fused<<<258, 1024>>>(w_hh, hidden, enc, emb, input_id);
    k2_finish_cat<<<2, 1024>>>();
    k3_comb<<<128, 1024>>>(comb_w, comb_b);
    k4_wih<<<192, 1024>>>(w_ih);
    k5_gates<<<2, 1024>>>(b_ih, b_hh, hidden);
    k6_out<<<296, 1024>>>(out_w, out_b);
    k7_lse<<<1, 1024>>>();
    k8_write<<<(out_size + 255) / 256, 256>>>(out, out_size);
}